// round 1
// baseline (speedup 1.0000x reference)
#include <cuda_runtime.h>
#include <cuda_bf16.h>
#include <math.h>

// Problem constants
#define BATCH 2
#define SEQ   2048
#define HID   4096
#define NH    32
#define NKV   8
#define HD    128
#define MROWS (BATCH*SEQ)         // 4096
#define KVW   (NKV*HD)            // 1024
#define QKVN  (HID + 2*KVW)       // 6144
#define SCALE_F 0.08838834764831845f  // 128^-0.5

// ---------------- scratch (device globals; allocation-free) ----------------
__device__ float g_qkv[(size_t)MROWS * QKVN];   // raw [4096, 6144]  (Q|K|V)
__device__ float g_q  [(size_t)MROWS * HID];    // roped Q [4096, 4096]
__device__ float g_k  [(size_t)MROWS * KVW];    // roped K [4096, 1024]
__device__ float g_attn[(size_t)MROWS * HID];   // attention out [4096, 4096]

// ---------------- SGEMM: C = A @ B^T (+bias), NT, fp32 ----------------
// BM=BN=128, BK=16, 256 threads, 8x8 microtile.
// Fused-QKV mode: column block selects Wq / Wk(+bk) / Wv(+bv).
#define GBM 128
#define GBN 128
#define GBK 16
#define ASTR 132   // padded smem stride (multiple of 4 floats -> 16B aligned rows)

__global__ void __launch_bounds__(256) sgemm_nt_kernel(
    const float* __restrict__ A,
    const float* __restrict__ Wq, const float* __restrict__ Wk, const float* __restrict__ Wv,
    const float* __restrict__ biask, const float* __restrict__ biasv,
    float* __restrict__ C, int M, int N, int K)
{
    __shared__ float As[GBK][ASTR];
    __shared__ float Bs[GBK][ASTR];

    const int tid = threadIdx.x;
    const int bm0 = blockIdx.y * GBM;
    const int bn0 = blockIdx.x * GBN;

    const float* B;
    const float* bias = nullptr;
    int boff = bn0;
    if (bn0 < HID)            { B = Wq; }
    else if (bn0 < HID + KVW) { B = Wk; boff = bn0 - HID;       bias = biask; }
    else                      { B = Wv; boff = bn0 - HID - KVW; bias = biasv; }

    const int lrow = tid >> 2;          // 0..63
    const int lk4  = (tid & 3) * 4;     // 0,4,8,12
    const float* Aptr = A + (size_t)(bm0 + lrow) * K + lk4;
    const float* Bptr = B + (size_t)(boff + lrow) * K + lk4;

    const int tx = tid & 15, ty = tid >> 4;

    float acc[8][8];
    #pragma unroll
    for (int i = 0; i < 8; i++)
        #pragma unroll
        for (int j = 0; j < 8; j++) acc[i][j] = 0.f;

    for (int kt = 0; kt < K; kt += GBK) {
        float4 a0 = *(const float4*)(Aptr + kt);
        float4 a1 = *(const float4*)(Aptr + (size_t)64 * K + kt);
        float4 b0 = *(const float4*)(Bptr + kt);
        float4 b1 = *(const float4*)(Bptr + (size_t)64 * K + kt);
        __syncthreads();   // previous compute done before overwriting smem
        As[lk4+0][lrow]    = a0.x; As[lk4+1][lrow]    = a0.y; As[lk4+2][lrow]    = a0.z; As[lk4+3][lrow]    = a0.w;
        As[lk4+0][lrow+64] = a1.x; As[lk4+1][lrow+64] = a1.y; As[lk4+2][lrow+64] = a1.z; As[lk4+3][lrow+64] = a1.w;
        Bs[lk4+0][lrow]    = b0.x; Bs[lk4+1][lrow]    = b0.y; Bs[lk4+2][lrow]    = b0.z; Bs[lk4+3][lrow]    = b0.w;
        Bs[lk4+0][lrow+64] = b1.x; Bs[lk4+1][lrow+64] = b1.y; Bs[lk4+2][lrow+64] = b1.z; Bs[lk4+3][lrow+64] = b1.w;
        __syncthreads();

        #pragma unroll
        for (int kk = 0; kk < GBK; kk++) {
            float4 af0 = *(const float4*)&As[kk][ty*8];
            float4 af1 = *(const float4*)&As[kk][ty*8 + 4];
            float4 bf0 = *(const float4*)&Bs[kk][tx*8];
            float4 bf1 = *(const float4*)&Bs[kk][tx*8 + 4];
            float av[8] = {af0.x, af0.y, af0.z, af0.w, af1.x, af1.y, af1.z, af1.w};
            float bw[8] = {bf0.x, bf0.y, bf0.z, bf0.w, bf1.x, bf1.y, bf1.z, bf1.w};
            #pragma unroll
            for (int i = 0; i < 8; i++)
                #pragma unroll
                for (int j = 0; j < 8; j++)
                    acc[i][j] = fmaf(av[i], bw[j], acc[i][j]);
        }
    }

    float bvals[8];
    #pragma unroll
    for (int j = 0; j < 8; j++)
        bvals[j] = bias ? bias[boff + tx*8 + j] : 0.f;

    #pragma unroll
    for (int i = 0; i < 8; i++) {
        float* cp = C + (size_t)(bm0 + ty*8 + i) * N + bn0 + tx*8;
        float4 o0, o1;
        o0.x = acc[i][0] + bvals[0]; o0.y = acc[i][1] + bvals[1];
        o0.z = acc[i][2] + bvals[2]; o0.w = acc[i][3] + bvals[3];
        o1.x = acc[i][4] + bvals[4]; o1.y = acc[i][5] + bvals[5];
        o1.z = acc[i][6] + bvals[6]; o1.w = acc[i][7] + bvals[7];
        *(float4*)cp       = o0;
        *(float4*)(cp + 4) = o1;
    }
}

// ---------------- RoPE ----------------
// out[d]     = x[2d]*cos - x[2d+1]*sin      (d in [0,64))
// out[d+64]  = x[2d]*sin + x[2d+1]*cos
// heads 0..31 -> Q (from qkv cols [0,4096)), heads 32..39 -> K (cols [4096,5120))
__global__ void rope_kernel(const float* __restrict__ qkv,
                            const float* __restrict__ cosb,
                            const float* __restrict__ sinb,
                            float* __restrict__ qout,
                            float* __restrict__ kout)
{
    const int total = MROWS * (NH + NKV) * 64;
    int idx = blockIdx.x * blockDim.x + threadIdx.x;
    if (idx >= total) return;
    int d    = idx & 63;
    int t    = idx >> 6;
    int head = t % (NH + NKV);
    int m    = t / (NH + NKV);
    int s    = m & (SEQ - 1);
    float c  = cosb[s*64 + d];
    float sn = sinb[s*64 + d];
    if (head < NH) {
        const float* src = qkv + (size_t)m * QKVN + head * HD;
        float e = src[2*d], o = src[2*d + 1];
        float* dst = qout + (size_t)m * HID + head * HD;
        dst[d]      = e*c  - o*sn;
        dst[d + 64] = e*sn + o*c;
    } else {
        int kh = head - NH;
        const float* src = qkv + (size_t)m * QKVN + HID + kh * HD;
        float e = src[2*d], o = src[2*d + 1];
        float* dst = kout + (size_t)m * KVW + kh * HD;
        dst[d]      = e*c  - o*sn;
        dst[d + 64] = e*sn + o*c;
    }
}

// ---------------- Flash attention (fp32, non-causal, GQA 4:1) ----------------
// Block: 64 queries, one (b,h); iterate key tiles of 64. 256 threads.
// smem: QsT[128][68] | KVs (KsT[128][68] reused as Vs[64][132]) | Ss[64][65] | stats
#define QT_STR 68
#define V_STR  132
#define S_STR  65
#define ATT_SMEM_FLOATS (128*QT_STR + 128*QT_STR + 64*S_STR + 3*64)
#define ATT_SMEM_BYTES  (ATT_SMEM_FLOATS * 4)

__global__ void __launch_bounds__(256) attn_kernel(
    const float* __restrict__ Q,    // [4096, 4096] roped
    const float* __restrict__ Kr,   // [4096, 1024] roped
    const float* __restrict__ QKV,  // raw, V at col 5120
    float* __restrict__ O)          // [4096, 4096] (b,s,h,d)
{
    extern __shared__ float sm[];
    float* QsT = sm;                       // 128*68
    float* KVs = sm + 128*QT_STR;          // 128*68 (>= 64*132)
    float* Ss  = KVs + 128*QT_STR;         // 64*65
    float* m_s = Ss + 64*S_STR;
    float* l_s = m_s + 64;
    float* al_s = l_s + 64;

    const int tid = threadIdx.x;
    const int b  = blockIdx.z;
    const int h  = blockIdx.y;
    const int q0 = blockIdx.x * 64;
    const int kh = h >> 2;                 // N_REP = 4
    const int trow = tid >> 4;             // 0..15 -> rows trow*4..+3
    const int tcol = tid & 15;             // S cols tcol*4 ; O dims tcol*8

    // Q tile -> QsT[d][row]
    {
        const int d4 = (tid & 31) * 4;
        const float* qb = Q + (size_t)(b*SEQ + q0) * HID + h*HD + d4;
        #pragma unroll
        for (int l = 0; l < 8; ++l) {
            int r = (tid >> 5) + 8*l;
            float4 v = *(const float4*)(qb + (size_t)r * HID);
            QsT[(d4+0)*QT_STR + r] = v.x;
            QsT[(d4+1)*QT_STR + r] = v.y;
            QsT[(d4+2)*QT_STR + r] = v.z;
            QsT[(d4+3)*QT_STR + r] = v.w;
        }
    }
    if (tid < 64) { m_s[tid] = -INFINITY; l_s[tid] = 0.f; }

    float oacc[4][8];
    #pragma unroll
    for (int i = 0; i < 4; i++)
        #pragma unroll
        for (int j = 0; j < 8; j++) oacc[i][j] = 0.f;

    const float* kb = Kr  + (size_t)(b*SEQ) * KVW  + kh*HD;
    const float* vb = QKV + (size_t)(b*SEQ) * QKVN + HID + KVW + kh*HD;

    for (int kt = 0; kt < SEQ; kt += 64) {
        __syncthreads();   // previous P@V finished with KVs
        // K tile -> KsT[d][key]
        {
            const int d4 = (tid & 31) * 4;
            const float* kbt = kb + (size_t)kt * KVW + d4;
            #pragma unroll
            for (int l = 0; l < 8; ++l) {
                int r = (tid >> 5) + 8*l;
                float4 v = *(const float4*)(kbt + (size_t)r * KVW);
                KVs[(d4+0)*QT_STR + r] = v.x;
                KVs[(d4+1)*QT_STR + r] = v.y;
                KVs[(d4+2)*QT_STR + r] = v.z;
                KVs[(d4+3)*QT_STR + r] = v.w;
            }
        }
        __syncthreads();

        // S = scale * Q K^T  (4x4 per thread)
        float sacc[4][4];
        #pragma unroll
        for (int i = 0; i < 4; i++)
            #pragma unroll
            for (int j = 0; j < 4; j++) sacc[i][j] = 0.f;
        #pragma unroll 8
        for (int d = 0; d < HD; ++d) {
            float4 a  = *(const float4*)&QsT[d*QT_STR + trow*4];
            float4 bb = *(const float4*)&KVs[d*QT_STR + tcol*4];
            float av[4] = {a.x, a.y, a.z, a.w};
            float bw[4] = {bb.x, bb.y, bb.z, bb.w};
            #pragma unroll
            for (int i = 0; i < 4; i++)
                #pragma unroll
                for (int j = 0; j < 4; j++)
                    sacc[i][j] = fmaf(av[i], bw[j], sacc[i][j]);
        }
        #pragma unroll
        for (int i = 0; i < 4; i++)
            #pragma unroll
            for (int j = 0; j < 4; j++)
                Ss[(trow*4+i)*S_STR + tcol*4 + j] = sacc[i][j] * SCALE_F;
        __syncthreads();   // S visible; everyone done with KsT

        // V tile -> Vs[key][d] (reuses KVs)
        {
            const int d4 = (tid & 31) * 4;
            const float* vbt = vb + (size_t)kt * QKVN + d4;
            #pragma unroll
            for (int l = 0; l < 8; ++l) {
                int r = (tid >> 5) + 8*l;
                float4 v = *(const float4*)(vbt + (size_t)r * QKVN);
                *(float4*)&KVs[r*V_STR + d4] = v;
            }
        }

        // online softmax: 4 lanes per row
        {
            int row = tid >> 2, seg = tid & 3;
            float* srow = Ss + row*S_STR + seg*16;
            float mx = srow[0];
            #pragma unroll
            for (int k2 = 1; k2 < 16; k2++) mx = fmaxf(mx, srow[k2]);
            mx = fmaxf(mx, __shfl_xor_sync(0xffffffffu, mx, 1));
            mx = fmaxf(mx, __shfl_xor_sync(0xffffffffu, mx, 2));
            float m_old = m_s[row];
            float m_new = fmaxf(m_old, mx);
            float sum = 0.f;
            #pragma unroll
            for (int k2 = 0; k2 < 16; k2++) {
                float p = __expf(srow[k2] - m_new);
                srow[k2] = p;
                sum += p;
            }
            sum += __shfl_xor_sync(0xffffffffu, sum, 1);
            sum += __shfl_xor_sync(0xffffffffu, sum, 2);
            if (seg == 0) {
                float alpha = __expf(m_old - m_new);
                l_s[row]  = l_s[row] * alpha + sum;
                m_s[row]  = m_new;
                al_s[row] = alpha;
            }
        }
        __syncthreads();   // P, alpha, V all ready

        // rescale + O += P @ V
        #pragma unroll
        for (int i = 0; i < 4; i++) {
            float al = al_s[trow*4 + i];
            #pragma unroll
            for (int j = 0; j < 8; j++) oacc[i][j] *= al;
        }
        #pragma unroll 4
        for (int k2 = 0; k2 < 64; k2++) {
            float av[4];
            #pragma unroll
            for (int i = 0; i < 4; i++) av[i] = Ss[(trow*4+i)*S_STR + k2];
            float4 b0 = *(const float4*)&KVs[k2*V_STR + tcol*8];
            float4 b1 = *(const float4*)&KVs[k2*V_STR + tcol*8 + 4];
            float bw[8] = {b0.x, b0.y, b0.z, b0.w, b1.x, b1.y, b1.z, b1.w};
            #pragma unroll
            for (int i = 0; i < 4; i++)
                #pragma unroll
                for (int j = 0; j < 8; j++)
                    oacc[i][j] = fmaf(av[i], bw[j], oacc[i][j]);
        }
    }

    // epilogue: normalize and store
    #pragma unroll
    for (int i = 0; i < 4; i++) {
        float inv = 1.f / l_s[trow*4 + i];
        float* op = O + (size_t)(b*SEQ + q0 + trow*4 + i) * HID + h*HD + tcol*8;
        float4 o0, o1;
        o0.x = oacc[i][0]*inv; o0.y = oacc[i][1]*inv; o0.z = oacc[i][2]*inv; o0.w = oacc[i][3]*inv;
        o1.x = oacc[i][4]*inv; o1.y = oacc[i][5]*inv; o1.z = oacc[i][6]*inv; o1.w = oacc[i][7]*inv;
        *(float4*)op       = o0;
        *(float4*)(op + 4) = o1;
    }
}

// ---------------- launch ----------------
extern "C" void kernel_launch(void* const* d_in, const int* in_sizes, int n_in,
                              void* d_out, int out_size)
{
    const float* X  = (const float*)d_in[0];
    const float* cs = (const float*)d_in[1];
    const float* sn = (const float*)d_in[2];
    const float* Wq = (const float*)d_in[3];
    const float* Wk = (const float*)d_in[4];
    const float* bk = (const float*)d_in[5];
    const float* Wv = (const float*)d_in[6];
    const float* bv = (const float*)d_in[7];
    const float* Wo = (const float*)d_in[8];
    float* out = (float*)d_out;

    float *qkv, *qr, *kr, *ao;
    cudaGetSymbolAddress((void**)&qkv, g_qkv);
    cudaGetSymbolAddress((void**)&qr,  g_q);
    cudaGetSymbolAddress((void**)&kr,  g_k);
    cudaGetSymbolAddress((void**)&ao,  g_attn);

    // 1) fused QKV projection: [4096,6144]
    sgemm_nt_kernel<<<dim3(QKVN/GBN, MROWS/GBM), 256>>>(
        X, Wq, Wk, Wv, bk, bv, qkv, MROWS, QKVN, HID);

    // 2) RoPE on Q and K
    {
        int total = MROWS * (NH + NKV) * 64;
        rope_kernel<<<(total + 255) / 256, 256>>>(qkv, cs, sn, qr, kr);
    }

    // 3) attention
    cudaFuncSetAttribute(attn_kernel, cudaFuncAttributeMaxDynamicSharedMemorySize, ATT_SMEM_BYTES);
    attn_kernel<<<dim3(SEQ/64, NH, BATCH), 256, ATT_SMEM_BYTES>>>(qr, kr, qkv, ao);

    // 4) output projection -> d_out
    sgemm_nt_kernel<<<dim3(HID/GBN, MROWS/GBM), 256>>>(
        ao, Wo, Wo, Wo, nullptr, nullptr, out, MROWS, HID, HID);
}

// round 16
// speedup vs baseline: 1.6045x; 1.6045x over previous
#include <cuda_runtime.h>
#include <cuda_bf16.h>
#include <math.h>
#include <stdint.h>

// ---------------- problem constants ----------------
#define BATCH 2
#define SEQ   2048
#define HID   4096
#define NH    32
#define NKV   8
#define HD    128
#define MROWS (BATCH*SEQ)         // 4096
#define KVW   (NKV*HD)            // 1024
#define QKVN  (HID + 2*KVW)       // 6144
#define SCALE_F 0.08838834764831845f

// ---------------- scratch (device globals) ----------------
__device__ float g_qkv [(size_t)MROWS * QKVN];
__device__ float g_q   [(size_t)MROWS * HID];
__device__ float g_k   [(size_t)MROWS * KVW];
__device__ float g_attn[(size_t)MROWS * HID];

__device__ __nv_bfloat16 g_xh [(size_t)MROWS * HID];
__device__ __nv_bfloat16 g_xl [(size_t)MROWS * HID];
__device__ __nv_bfloat16 g_wh [(size_t)QKVN  * HID];
__device__ __nv_bfloat16 g_wl [(size_t)QKVN  * HID];
__device__ __nv_bfloat16 g_woh[(size_t)HID   * HID];
__device__ __nv_bfloat16 g_wol[(size_t)HID   * HID];
__device__ __nv_bfloat16 g_aoh[(size_t)MROWS * HID];
__device__ __nv_bfloat16 g_aol[(size_t)MROWS * HID];

// ---------------- PTX helpers (base ISA only; NO tcgen05/TMA) ----------------
__device__ __forceinline__ uint32_t smem_u32(const void* p) {
    uint32_t a;
    asm("{ .reg .u64 t; cvta.to.shared.u64 t, %1; cvt.u32.u64 %0, t; }" : "=r"(a) : "l"(p));
    return a;
}
__device__ __forceinline__ void cpa16(uint32_t dst, const void* src) {
    asm volatile("cp.async.cg.shared.global [%0], [%1], 16;" :: "r"(dst), "l"(src));
}
#define CP_COMMIT() asm volatile("cp.async.commit_group;" ::: "memory")
#define CP_WAIT1()  asm volatile("cp.async.wait_group 1;" ::: "memory")
#define SWZ(o) ((o) ^ (((o) >> 3) & 0x70))

__device__ __forceinline__ void ldsm4(uint32_t* r, uint32_t addr) {
    asm volatile("ldmatrix.sync.aligned.m8n8.x4.shared.b16 {%0,%1,%2,%3}, [%4];"
                 : "=r"(r[0]), "=r"(r[1]), "=r"(r[2]), "=r"(r[3]) : "r"(addr));
}
__device__ __forceinline__ void mma16816(float* c, const uint32_t* a, const uint32_t* b) {
    asm volatile("mma.sync.aligned.m16n8k16.row.col.f32.bf16.bf16.f32 "
                 "{%0,%1,%2,%3}, {%4,%5,%6,%7}, {%8,%9}, {%0,%1,%2,%3};"
                 : "+f"(c[0]), "+f"(c[1]), "+f"(c[2]), "+f"(c[3])
                 : "r"(a[0]), "r"(a[1]), "r"(a[2]), "r"(a[3]), "r"(b[0]), "r"(b[1]));
}

// ---------------- hi/lo bf16 split conversion ----------------
__global__ void cvt_hilo_kernel(const float* __restrict__ src,
                                __nv_bfloat16* __restrict__ h,
                                __nv_bfloat16* __restrict__ l, int n4)
{
    int i = blockIdx.x * blockDim.x + threadIdx.x;
    if (i >= n4) return;
    float4 v = ((const float4*)src)[i];
    __nv_bfloat16 h0 = __float2bfloat16(v.x);
    __nv_bfloat16 h1 = __float2bfloat16(v.y);
    __nv_bfloat16 h2 = __float2bfloat16(v.z);
    __nv_bfloat16 h3 = __float2bfloat16(v.w);
    __nv_bfloat16 l0 = __float2bfloat16(v.x - __bfloat162float(h0));
    __nv_bfloat16 l1 = __float2bfloat16(v.y - __bfloat162float(h1));
    __nv_bfloat16 l2 = __float2bfloat16(v.z - __bfloat162float(h2));
    __nv_bfloat16 l3 = __float2bfloat16(v.w - __bfloat162float(h3));
    __nv_bfloat162* hp = (__nv_bfloat162*)h;
    __nv_bfloat162* lp = (__nv_bfloat162*)l;
    hp[2*i]   = __nv_bfloat162(h0, h1);
    hp[2*i+1] = __nv_bfloat162(h2, h3);
    lp[2*i]   = __nv_bfloat162(l0, l1);
    lp[2*i+1] = __nv_bfloat162(l2, l3);
}

// ---------------- mma.sync bf16x3 GEMM: C = A @ B^T, fp32 out ----------------
// BM=BN=128, BK=32, 256 threads (8 warps as 2x4), warp tile 64x32.
// smem tile row = [h(32 bf16) | l(32 bf16)] = 128B, SW128 swizzle.
// 3-stage cp.async pipeline: 3 * (16KB A + 16KB B) = 96KB.
#define GBM 128
#define GBN 128
#define GBK 32
#define STAGE_B 32768
#define TILE_B  16384
#define GEMM_SMEM (3*STAGE_B)

__device__ __forceinline__ void gemm_load_stage(uint32_t sbase,
    const __nv_bfloat16* Agh, const __nv_bfloat16* Agl,
    const __nv_bfloat16* Bgh, const __nv_bfloat16* Bgl,
    int k0, int K, int tid)
{
    #pragma unroll
    for (int m = 0; m < 4; ++m) {                       // A: 1024 16B chunks
        int o = tid + m * 256;
        int r = o >> 3, c = o & 7;
        uint32_t soff = SWZ((uint32_t)(r * 128 + c * 16));
        const __nv_bfloat16* src = (c < 4) ? (Agh + (size_t)r * K + k0 + c * 8)
                                           : (Agl + (size_t)r * K + k0 + (c & 3) * 8);
        cpa16(sbase + soff, src);
    }
    #pragma unroll
    for (int m = 0; m < 4; ++m) {                       // B: 1024 16B chunks
        int o = tid + m * 256;
        int r = o >> 3, c = o & 7;
        uint32_t soff = SWZ((uint32_t)(r * 128 + c * 16));
        const __nv_bfloat16* src = (c < 4) ? (Bgh + (size_t)r * K + k0 + c * 8)
                                           : (Bgl + (size_t)r * K + k0 + (c & 3) * 8);
        cpa16(sbase + TILE_B + soff, src);
    }
}

// load 4 A mfrags (16x16 each) for pass p (0=h,1=l), kstep kk0
__device__ __forceinline__ void load_afrag(uint32_t a[4][4], uint32_t sA,
                                           int wr, int lane, int p, int kk0)
{
    int r  = lane & 15;
    int ch = (lane >> 4) * 16;
    #pragma unroll
    for (int i = 0; i < 4; ++i) {
        uint32_t byte = (uint32_t)((wr * 64 + i * 16 + r) * 128 + p * 64 + kk0 * 2 + ch);
        ldsm4(a[i], sA + SWZ(byte));
    }
}
// load 4 B nfrags (two x4 loads; each covers 2 nfrags of 8x16)
__device__ __forceinline__ void load_bfrag(uint32_t b[4][2], uint32_t sB,
                                           int wc, int lane, int p, int kk0)
{
    int rsub = ((lane >> 4) & 1) * 8 + (lane & 7);
    int chb  = ((lane >> 3) & 1) * 16;
    #pragma unroll
    for (int j2 = 0; j2 < 2; ++j2) {
        uint32_t byte = (uint32_t)((wc * 32 + j2 * 16 + rsub) * 128 + p * 64 + kk0 * 2 + chb);
        uint32_t t[4];
        ldsm4(t, sB + SWZ(byte));
        b[j2*2  ][0] = t[0]; b[j2*2  ][1] = t[1];
        b[j2*2+1][0] = t[2]; b[j2*2+1][1] = t[3];
    }
}

__device__ __forceinline__ void mma_all(float c[4][4][4], uint32_t a[4][4], uint32_t b[4][2]) {
    #pragma unroll
    for (int i = 0; i < 4; ++i)
        #pragma unroll
        for (int j = 0; j < 4; ++j)
            mma16816(c[i][j], a[i], b[j]);
}

__global__ void __launch_bounds__(256, 2) mma_gemm_kernel(
    const __nv_bfloat16* __restrict__ Ah, const __nv_bfloat16* __restrict__ Al,
    const __nv_bfloat16* __restrict__ Bh, const __nv_bfloat16* __restrict__ Bl,
    float* __restrict__ C, int N, int K, int grid_n)
{
    extern __shared__ char smem[];
    uint32_t sb = smem_u32(smem);
    const int tid = threadIdx.x, lane = tid & 31, wid = tid >> 5;
    const int wr = wid >> 2, wc = wid & 3;

    // grid swizzle: groups of 8 M-tiles per N sweep (A panel stays in L2)
    int bid = blockIdx.x;
    int per_group = 8 * grid_n;
    int g = bid / per_group, r = bid % per_group;
    int by = g * 8 + (r & 7);
    int bx = r >> 3;
    const int bm0 = by * GBM;
    const int bn0 = bx * GBN;

    const __nv_bfloat16* Agh = Ah + (size_t)bm0 * K;
    const __nv_bfloat16* Agl = Al + (size_t)bm0 * K;
    const __nv_bfloat16* Bgh = Bh + (size_t)bn0 * K;
    const __nv_bfloat16* Bgl = Bl + (size_t)bn0 * K;

    float acc[4][4][4];
    #pragma unroll
    for (int i = 0; i < 4; ++i)
        #pragma unroll
        for (int j = 0; j < 4; ++j)
            #pragma unroll
            for (int q = 0; q < 4; ++q) acc[i][j][q] = 0.f;

    const int NC = K / GBK;     // 128
    gemm_load_stage(sb,           Agh, Agl, Bgh, Bgl, 0,   K, tid); CP_COMMIT();
    gemm_load_stage(sb + STAGE_B, Agh, Agl, Bgh, Bgl, GBK, K, tid); CP_COMMIT();

    for (int i = 0; i < NC; ++i) {
        CP_WAIT1();
        __syncthreads();
        if (i + 2 < NC)
            gemm_load_stage(sb + ((i + 2) % 3) * STAGE_B, Agh, Agl, Bgh, Bgl, (i + 2) * GBK, K, tid);
        CP_COMMIT();

        const uint32_t sA = sb + (i % 3) * STAGE_B;
        const uint32_t sB = sA + TILE_B;
        #pragma unroll
        for (int kk = 0; kk < 2; ++kk) {
            const int kk0 = kk * 16;
            uint32_t a[4][4], b[4][2];
            load_bfrag(b, sB, wc, lane, 0, kk0);     // Bh
            load_afrag(a, sA, wr, lane, 0, kk0);     // Ah
            mma_all(acc, a, b);                      // Ah*Bh
            load_afrag(a, sA, wr, lane, 1, kk0);     // Al
            mma_all(acc, a, b);                      // Al*Bh
            load_bfrag(b, sB, wc, lane, 1, kk0);     // Bl
            load_afrag(a, sA, wr, lane, 0, kk0);     // Ah again
            mma_all(acc, a, b);                      // Ah*Bl
        }
    }
    __syncthreads();

    // epilogue: direct float2 stores
    const int rbase = bm0 + wr * 64 + (lane >> 2);
    const int cbase = bn0 + wc * 32 + (lane & 3) * 2;
    #pragma unroll
    for (int i = 0; i < 4; ++i) {
        #pragma unroll
        for (int j = 0; j < 4; ++j) {
            int row = rbase + i * 16;
            int col = cbase + j * 8;
            *(float2*)&C[(size_t)row * N + col]       = make_float2(acc[i][j][0], acc[i][j][1]);
            *(float2*)&C[(size_t)(row + 8) * N + col] = make_float2(acc[i][j][2], acc[i][j][3]);
        }
    }
}

// ---------------- RoPE (adds bk to K before rotation) ----------------
__global__ void rope_kernel(const float* __restrict__ qkv,
                            const float* __restrict__ cosb,
                            const float* __restrict__ sinb,
                            const float* __restrict__ bk,
                            float* __restrict__ qout,
                            float* __restrict__ kout)
{
    const int total = MROWS * (NH + NKV) * 64;
    int idx = blockIdx.x * blockDim.x + threadIdx.x;
    if (idx >= total) return;
    int d    = idx & 63;
    int t    = idx >> 6;
    int head = t % (NH + NKV);
    int m    = t / (NH + NKV);
    int s    = m & (SEQ - 1);
    float c  = cosb[s*64 + d];
    float sn = sinb[s*64 + d];
    if (head < NH) {
        const float* src = qkv + (size_t)m * QKVN + head * HD;
        float e = src[2*d], o = src[2*d + 1];
        float* dst = qout + (size_t)m * HID + head * HD;
        dst[d]      = e*c  - o*sn;
        dst[d + 64] = e*sn + o*c;
    } else {
        int kh = head - NH;
        const float* src = qkv + (size_t)m * QKVN + HID + kh * HD;
        float e = src[2*d]     + bk[kh*HD + 2*d];
        float o = src[2*d + 1] + bk[kh*HD + 2*d + 1];
        float* dst = kout + (size_t)m * KVW + kh * HD;
        dst[d]      = e*c  - o*sn;
        dst[d + 64] = e*sn + o*c;
    }
}

// ---------------- Flash attention (fp32, adds bv to V) ----------------
#define QT_STR 68
#define V_STR  132
#define S_STR  65
#define ATT_SMEM_FLOATS (128*QT_STR + 128*QT_STR + 64*S_STR + 3*64)
#define ATT_SMEM_BYTES  (ATT_SMEM_FLOATS * 4)

__global__ void __launch_bounds__(256) attn_kernel(
    const float* __restrict__ Q,
    const float* __restrict__ Kr,
    const float* __restrict__ QKV,
    const float* __restrict__ bv,
    float* __restrict__ O)
{
    extern __shared__ float sm[];
    float* QsT = sm;
    float* KVs = sm + 128*QT_STR;
    float* Ss  = KVs + 128*QT_STR;
    float* m_s = Ss + 64*S_STR;
    float* l_s = m_s + 64;
    float* al_s = l_s + 64;

    const int tid = threadIdx.x;
    const int b  = blockIdx.z;
    const int h  = blockIdx.y;
    const int q0 = blockIdx.x * 64;
    const int kh = h >> 2;
    const int trow = tid >> 4;
    const int tcol = tid & 15;

    {
        const int d4 = (tid & 31) * 4;
        const float* qb = Q + (size_t)(b*SEQ + q0) * HID + h*HD + d4;
        #pragma unroll
        for (int l = 0; l < 8; ++l) {
            int r = (tid >> 5) + 8*l;
            float4 v = *(const float4*)(qb + (size_t)r * HID);
            QsT[(d4+0)*QT_STR + r] = v.x;
            QsT[(d4+1)*QT_STR + r] = v.y;
            QsT[(d4+2)*QT_STR + r] = v.z;
            QsT[(d4+3)*QT_STR + r] = v.w;
        }
    }
    if (tid < 64) { m_s[tid] = -INFINITY; l_s[tid] = 0.f; }

    float oacc[4][8];
    #pragma unroll
    for (int i = 0; i < 4; i++)
        #pragma unroll
        for (int j = 0; j < 8; j++) oacc[i][j] = 0.f;

    const float* kb = Kr  + (size_t)(b*SEQ) * KVW  + kh*HD;
    const float* vb = QKV + (size_t)(b*SEQ) * QKVN + HID + KVW + kh*HD;
    const int d4v = (tid & 31) * 4;
    float4 bvv = *(const float4*)(bv + kh*HD + d4v);

    for (int kt = 0; kt < SEQ; kt += 64) {
        __syncthreads();
        {
            const int d4 = (tid & 31) * 4;
            const float* kbt = kb + (size_t)kt * KVW + d4;
            #pragma unroll
            for (int l = 0; l < 8; ++l) {
                int r = (tid >> 5) + 8*l;
                float4 v = *(const float4*)(kbt + (size_t)r * KVW);
                KVs[(d4+0)*QT_STR + r] = v.x;
                KVs[(d4+1)*QT_STR + r] = v.y;
                KVs[(d4+2)*QT_STR + r] = v.z;
                KVs[(d4+3)*QT_STR + r] = v.w;
            }
        }
        __syncthreads();

        float sacc[4][4];
        #pragma unroll
        for (int i = 0; i < 4; i++)
            #pragma unroll
            for (int j = 0; j < 4; j++) sacc[i][j] = 0.f;
        #pragma unroll 8
        for (int d = 0; d < HD; ++d) {
            float4 a  = *(const float4*)&QsT[d*QT_STR + trow*4];
            float4 bb = *(const float4*)&KVs[d*QT_STR + tcol*4];
            float av[4] = {a.x, a.y, a.z, a.w};
            float bw[4] = {bb.x, bb.y, bb.z, bb.w};
            #pragma unroll
            for (int i = 0; i < 4; i++)
                #pragma unroll
                for (int j = 0; j < 4; j++)
                    sacc[i][j] = fmaf(av[i], bw[j], sacc[i][j]);
        }
        #pragma unroll
        for (int i = 0; i < 4; i++)
            #pragma unroll
            for (int j = 0; j < 4; j++)
                Ss[(trow*4+i)*S_STR + tcol*4 + j] = sacc[i][j] * SCALE_F;
        __syncthreads();

        {
            const float* vbt = vb + (size_t)kt * QKVN + d4v;
            #pragma unroll
            for (int l = 0; l < 8; ++l) {
                int r = (tid >> 5) + 8*l;
                float4 v = *(const float4*)(vbt + (size_t)r * QKVN);
                v.x += bvv.x; v.y += bvv.y; v.z += bvv.z; v.w += bvv.w;
                *(float4*)&KVs[r*V_STR + d4v] = v;
            }
        }

        {
            int row = tid >> 2, seg = tid & 3;
            float* srow = Ss + row*S_STR + seg*16;
            float mx = srow[0];
            #pragma unroll
            for (int k2 = 1; k2 < 16; k2++) mx = fmaxf(mx, srow[k2]);
            mx = fmaxf(mx, __shfl_xor_sync(0xffffffffu, mx, 1));
            mx = fmaxf(mx, __shfl_xor_sync(0xffffffffu, mx, 2));
            float m_old = m_s[row];
            float m_new = fmaxf(m_old, mx);
            float sum = 0.f;
            #pragma unroll
            for (int k2 = 0; k2 < 16; k2++) {
                float p = __expf(srow[k2] - m_new);
                srow[k2] = p;
                sum += p;
            }
            sum += __shfl_xor_sync(0xffffffffu, sum, 1);
            sum += __shfl_xor_sync(0xffffffffu, sum, 2);
            if (seg == 0) {
                float alpha = __expf(m_old - m_new);
                l_s[row]  = l_s[row] * alpha + sum;
                m_s[row]  = m_new;
                al_s[row] = alpha;
            }
        }
        __syncthreads();

        #pragma unroll
        for (int i = 0; i < 4; i++) {
            float al = al_s[trow*4 + i];
            #pragma unroll
            for (int j = 0; j < 8; j++) oacc[i][j] *= al;
        }
        #pragma unroll 4
        for (int k2 = 0; k2 < 64; k2++) {
            float av[4];
            #pragma unroll
            for (int i = 0; i < 4; i++) av[i] = Ss[(trow*4+i)*S_STR + k2];
            float4 b0 = *(const float4*)&KVs[k2*V_STR + tcol*8];
            float4 b1 = *(const float4*)&KVs[k2*V_STR + tcol*8 + 4];
            float bw[8] = {b0.x, b0.y, b0.z, b0.w, b1.x, b1.y, b1.z, b1.w};
            #pragma unroll
            for (int i = 0; i < 4; i++)
                #pragma unroll
                for (int j = 0; j < 8; j++)
                    oacc[i][j] = fmaf(av[i], bw[j], oacc[i][j]);
        }
    }

    #pragma unroll
    for (int i = 0; i < 4; i++) {
        float inv = 1.f / l_s[trow*4 + i];
        float* op = O + (size_t)(b*SEQ + q0 + trow*4 + i) * HID + h*HD + tcol*8;
        float4 o0, o1;
        o0.x = oacc[i][0]*inv; o0.y = oacc[i][1]*inv; o0.z = oacc[i][2]*inv; o0.w = oacc[i][3]*inv;
        o1.x = oacc[i][4]*inv; o1.y = oacc[i][5]*inv; o1.z = oacc[i][6]*inv; o1.w = oacc[i][7]*inv;
        *(float4*)op       = o0;
        *(float4*)(op + 4) = o1;
    }
}

// ---------------- launch ----------------
extern "C" void kernel_launch(void* const* d_in, const int* in_sizes, int n_in,
                              void* d_out, int out_size)
{
    const float* X  = (const float*)d_in[0];
    const float* cs = (const float*)d_in[1];
    const float* sn = (const float*)d_in[2];
    const float* Wq = (const float*)d_in[3];
    const float* Wk = (const float*)d_in[4];
    const float* bk = (const float*)d_in[5];
    const float* Wv = (const float*)d_in[6];
    const float* bv = (const float*)d_in[7];
    const float* Wo = (const float*)d_in[8];
    float* out = (float*)d_out;

    float *qkv, *qr, *kr, *ao;
    __nv_bfloat16 *xh, *xl, *wh, *wl, *woh, *wol, *aoh, *aol;
    cudaGetSymbolAddress((void**)&qkv, g_qkv);
    cudaGetSymbolAddress((void**)&qr,  g_q);
    cudaGetSymbolAddress((void**)&kr,  g_k);
    cudaGetSymbolAddress((void**)&ao,  g_attn);
    cudaGetSymbolAddress((void**)&xh,  g_xh);
    cudaGetSymbolAddress((void**)&xl,  g_xl);
    cudaGetSymbolAddress((void**)&wh,  g_wh);
    cudaGetSymbolAddress((void**)&wl,  g_wl);
    cudaGetSymbolAddress((void**)&woh, g_woh);
    cudaGetSymbolAddress((void**)&wol, g_wol);
    cudaGetSymbolAddress((void**)&aoh, g_aoh);
    cudaGetSymbolAddress((void**)&aol, g_aol);

    cudaFuncSetAttribute(mma_gemm_kernel, cudaFuncAttributeMaxDynamicSharedMemorySize, GEMM_SMEM);
    cudaFuncSetAttribute(attn_kernel,     cudaFuncAttributeMaxDynamicSharedMemorySize, ATT_SMEM_BYTES);

    // 1) hi/lo bf16 splits of X and weights
    {
        int n4;
        n4 = MROWS*HID/4;  cvt_hilo_kernel<<<(n4+255)/256, 256>>>(X,  xh, xl, n4);
        n4 = HID*HID/4;    cvt_hilo_kernel<<<(n4+255)/256, 256>>>(Wq, wh, wl, n4);
        n4 = KVW*HID/4;    cvt_hilo_kernel<<<(n4+255)/256, 256>>>(Wk, wh + (size_t)HID*HID,       wl + (size_t)HID*HID,       n4);
        n4 = KVW*HID/4;    cvt_hilo_kernel<<<(n4+255)/256, 256>>>(Wv, wh + (size_t)(HID+KVW)*HID, wl + (size_t)(HID+KVW)*HID, n4);
        n4 = HID*HID/4;    cvt_hilo_kernel<<<(n4+255)/256, 256>>>(Wo, woh, wol, n4);
    }

    // 2) QKV projection (bias folded downstream)
    {
        int grid_n = QKVN / GBN, grid_m = MROWS / GBM;
        mma_gemm_kernel<<<grid_m * grid_n, 256, GEMM_SMEM>>>(
            xh, xl, wh, wl, qkv, QKVN, HID, grid_n);
    }

    // 3) RoPE (+bk)
    {
        int total = MROWS * (NH + NKV) * 64;
        rope_kernel<<<(total + 255) / 256, 256>>>(qkv, cs, sn, bk, qr, kr);
    }

    // 4) attention (+bv)
    attn_kernel<<<dim3(SEQ/64, NH, BATCH), 256, ATT_SMEM_BYTES>>>(qr, kr, qkv, bv, ao);

    // 5) hi/lo split of attention output, then O-projection -> d_out
    {
        int n4 = MROWS*HID/4;
        cvt_hilo_kernel<<<(n4+255)/256, 256>>>(ao, aoh, aol, n4);
    }
    {
        int grid_n = HID / GBN, grid_m = MROWS / GBM;
        mma_gemm_kernel<<<grid_m * grid_n, 256, GEMM_SMEM>>>(
            aoh, aol, woh, wol, out, HID, HID, grid_n);
    }
}